// round 6
// baseline (speedup 1.0000x reference)
#include <cuda_runtime.h>
#include <cuda_fp16.h>
#include <cstdint>

// ---------------- problem constants ----------------
#define PN         8
#define SEQ        4096
#define DIN        256
#define DOUT       256
#define LEVELS     7
#define TILE_M     128
#define KCH        64
#define NCHUNK     (DIN / KCH)          // 4
#define NTHREADS   512
#define M_PER_PATH 32768                // bpp * SEQ
#define M_TOTAL    (PN * M_PER_PATH)    // 262144
#define GRID       (M_TOTAL / TILE_M)   // 2048

// ---------------- device scratch (globals: no allocs) ----------------
__device__ __align__(16) __half g_w[LEVELS * DOUT * DIN];
__device__ int g_levels[PN];

// ---------------- smem layout (bytes) ----------------
#define A_OFF      0                    // 128 x 64 fp16 = 16 KB
#define B_OFF      16384                // 256 x 64 fp16 = 32 KB
#define BUF_BYTES  49152                // 48 KB per stage
#define SMEM_BYTES (2 * BUF_BYTES)      // 96 KB

#define SWZ(o) ((o) ^ (((o) >> 3) & 0x70))

// ---------------- helpers ----------------
static __device__ __forceinline__ uint32_t smem_u32(const void* p) {
    uint32_t a;
    asm("{ .reg .u64 t; cvta.to.shared.u64 t, %1; cvt.u32.u64 %0, t; }" : "=r"(a) : "l"(p));
    return a;
}

static __device__ __forceinline__ void cp16(uint32_t dst, const void* src) {
    asm volatile("cp.async.cg.shared.global [%0], [%1], 16;" :: "r"(dst), "l"(src) : "memory");
}
#define CP_COMMIT() asm volatile("cp.async.commit_group;" ::: "memory")
#define CP_WAIT0()  asm volatile("cp.async.wait_group 0;" ::: "memory")

static __device__ __forceinline__ void ldsm4(uint32_t* r, uint32_t addr) {
    asm volatile("ldmatrix.sync.aligned.m8n8.x4.shared.b16 {%0,%1,%2,%3}, [%4];"
                 : "=r"(r[0]), "=r"(r[1]), "=r"(r[2]), "=r"(r[3]) : "r"(addr));
}

static __device__ __forceinline__ void mma16816(float* d, const uint32_t* a, const uint32_t* b) {
    asm volatile(
        "mma.sync.aligned.m16n8k16.row.col.f32.f16.f16.f32 "
        "{%0,%1,%2,%3}, {%4,%5,%6,%7}, {%8,%9}, {%0,%1,%2,%3};"
        : "+f"(d[0]), "+f"(d[1]), "+f"(d[2]), "+f"(d[3])
        : "r"(a[0]), "r"(a[1]), "r"(a[2]), "r"(a[3]), "r"(b[0]), "r"(b[1]));
}

static __device__ __forceinline__ uint32_t pack_h2(float f0, float f1) {
    __half2 h = __floats2half2_rn(f0, f1);
    return *reinterpret_cast<uint32_t*>(&h);
}

// ---------------- prep pass: fp32 -> fp16 weights + assigned_bits dtype fix ----------------
__global__ void mpl_prep(const float* __restrict__ w, const void* __restrict__ abits) {
    int i = blockIdx.x * 256 + threadIdx.x;
    if (i < LEVELS * DOUT * DIN)
        g_w[i] = __float2half_rn(w[i]);
    if (blockIdx.x == 0 && threadIdx.x == 0) {
        const long long* p64 = (const long long*)abits;
        const int* p32 = (const int*)abits;
        bool is64 = true;
        #pragma unroll
        for (int p = 0; p < PN; p++) {
            long long v = p64[p];
            if (v < 0 || v >= LEVELS) is64 = false;
        }
        #pragma unroll
        for (int p = 0; p < PN; p++) {
            int lv = is64 ? (int)p64[p] : p32[p];
            if (lv < 0) lv = 0;
            if (lv >= LEVELS) lv = LEVELS - 1;
            g_levels[p] = lv;
        }
    }
}

// ---------------- main GEMM kernel: 512 threads, warp tile 64M x 32N ----------------
__global__ void __launch_bounds__(NTHREADS, 1)
mpl_kernel(const float* __restrict__ x, const float* __restrict__ bias,
           float* __restrict__ out)
{
    extern __shared__ char smem[];
    const uint32_t sb = smem_u32(smem);
    const int tid = threadIdx.x;
    const int wid = tid >> 5;
    const int lid = tid & 31;
    const int m0 = blockIdx.x * TILE_M;
    const int path = m0 / M_PER_PATH;
    const int level = g_levels[path];

    const float* xbase = x + (size_t)m0 * DIN;
    const __half* wb = g_w + (size_t)level * DOUT * DIN;

    // warp grid: 2(M) x 8(N); warp tile 64(M) x 32(N)
    const int mrow0 = (wid >> 3) * 64;
    const int ncol0 = (wid & 7) * 32;

    // per-lane ldmatrix address components
    const int g = lid >> 3;               // matrix group 0..3
    const int lr = lid & 7;               // row within matrix
    const int a_row = (g & 1) * 8 + lr;   // A: m,(m+8),m,(m+8)
    const int a_kb  = (g >> 1) * 16;      //    k,  k,  k+8, k+8 (bytes)
    const int b_row = (g >> 1) * 8 + lr;  // B: n,  n,  n+8, n+8
    const int b_kb  = (g & 1) * 16;       //    k, k+8,  k,  k+8 (bytes)

    float4 av[4];
    // ---------- prologue: fill buffer 0 with chunk 0 ----------
    {
        #pragma unroll
        for (int i = 0; i < 4; i++) {
            int idx = tid + i * NTHREADS;
            int r = idx >> 4, cg = idx & 15;
            av[i] = *(const float4*)(xbase + (size_t)r * DIN + cg * 4);
        }
        #pragma unroll
        for (int i = 0; i < 4; i++) {
            int idx = tid + i * NTHREADS;
            int n = idx >> 3, c8 = idx & 7;
            uint32_t sw = SWZ((uint32_t)(n * 128 + c8 * 16));
            cp16(sb + B_OFF + sw, wb + (size_t)n * DIN + c8 * 8);
        }
        CP_COMMIT();
        #pragma unroll
        for (int i = 0; i < 4; i++) {
            int idx = tid + i * NTHREADS;
            int r = idx >> 4, cg = idx & 15;
            uint32_t sw = SWZ((uint32_t)(r * 128 + cg * 8));
            *(uint2*)(smem + A_OFF + sw) =
                make_uint2(pack_h2(av[i].x, av[i].y), pack_h2(av[i].z, av[i].w));
        }
        CP_WAIT0();
        __syncthreads();
    }

    float acc[4][4][4];
    #pragma unroll
    for (int mt = 0; mt < 4; mt++)
        #pragma unroll
        for (int nt = 0; nt < 4; nt++)
            #pragma unroll
            for (int e = 0; e < 4; e++) acc[mt][nt][e] = 0.0f;

    // ---------- main loop over K chunks ----------
    #pragma unroll
    for (int kc = 0; kc < NCHUNK; kc++) {
        const uint32_t bufb = sb + (kc & 1) * BUF_BYTES;
        const uint32_t nbufb = sb + ((kc + 1) & 1) * BUF_BYTES;

        // prefetch next chunk: cp.async B, LDG A into regs (overlap with compute)
        if (kc < NCHUNK - 1) {
            const int kn = kc + 1;
            #pragma unroll
            for (int i = 0; i < 4; i++) {
                int idx = tid + i * NTHREADS;
                int n = idx >> 3, c8 = idx & 7;
                uint32_t sw = SWZ((uint32_t)(n * 128 + c8 * 16));
                cp16(nbufb + B_OFF + sw, wb + (size_t)n * DIN + kn * KCH + c8 * 8);
            }
            CP_COMMIT();
            #pragma unroll
            for (int i = 0; i < 4; i++) {
                int idx = tid + i * NTHREADS;
                int r = idx >> 4, cg = idx & 15;
                av[i] = *(const float4*)(xbase + (size_t)r * DIN + kn * KCH + cg * 4);
            }
        }

        // ---- compute current chunk: 4 k-steps ----
        const uint32_t abase = bufb + A_OFF;
        const uint32_t bbase = bufb + B_OFF;
        #pragma unroll
        for (int ks = 0; ks < 4; ks++) {
            uint32_t af[4][4];
            #pragma unroll
            for (int mt = 0; mt < 4; mt++) {
                uint32_t byte = (uint32_t)((mrow0 + mt * 16 + a_row) * 128 + ks * 32 + a_kb);
                ldsm4(af[mt], abase + SWZ(byte));
            }
            uint32_t bf[2][4];
            #pragma unroll
            for (int p = 0; p < 2; p++) {
                uint32_t byte = (uint32_t)((ncol0 + p * 16 + b_row) * 128 + ks * 32 + b_kb);
                ldsm4(bf[p], bbase + SWZ(byte));
            }
            #pragma unroll
            for (int mt = 0; mt < 4; mt++)
                #pragma unroll
                for (int p = 0; p < 2; p++) {
                    mma16816(acc[mt][2 * p + 0], af[mt], &bf[p][0]);
                    mma16816(acc[mt][2 * p + 1], af[mt], &bf[p][2]);
                }
        }

        // ---- stage next chunk's A; close pipeline stage ----
        if (kc < NCHUNK - 1) {
            #pragma unroll
            for (int i = 0; i < 4; i++) {
                int idx = tid + i * NTHREADS;
                int r = idx >> 4, cg = idx & 15;
                uint32_t sw = SWZ((uint32_t)(r * 128 + cg * 8));
                *(uint2*)(smem + ((kc + 1) & 1) * BUF_BYTES + A_OFF + sw) =
                    make_uint2(pack_h2(av[i].x, av[i].y), pack_h2(av[i].z, av[i].w));
            }
            CP_WAIT0();
            __syncthreads();
        }
    }

    // ---------- epilogue: bias + direct coalesced stores ----------
    const int qrow = lid >> 2;            // 0..7
    const int qcol = (lid & 3) * 2;       // 0,2,4,6
    float2 bv[4];
    #pragma unroll
    for (int nt = 0; nt < 4; nt++)
        bv[nt] = *(const float2*)(bias + ncol0 + nt * 8 + qcol);

    float* op = out + (size_t)m0 * DOUT;
    #pragma unroll
    for (int mt = 0; mt < 4; mt++) {
        int r0 = mrow0 + mt * 16 + qrow;
        #pragma unroll
        for (int nt = 0; nt < 4; nt++) {
            int c = ncol0 + nt * 8 + qcol;
            float2 v0, v1;
            v0.x = acc[mt][nt][0] + bv[nt].x;
            v0.y = acc[mt][nt][1] + bv[nt].y;
            v1.x = acc[mt][nt][2] + bv[nt].x;
            v1.y = acc[mt][nt][3] + bv[nt].y;
            *(float2*)(op + (size_t)r0 * DOUT + c) = v0;
            *(float2*)(op + (size_t)(r0 + 8) * DOUT + c) = v1;
        }
    }
}

// ---------------- launch: identify inputs BY ELEMENT COUNT (order-proof) ----------------
extern "C" void kernel_launch(void* const* d_in, const int* in_sizes, int n_in,
                              void* d_out, int out_size) {
    const float* x = nullptr;
    const float* weight_bank = nullptr;
    const float* bias = nullptr;
    const void* abits = nullptr;

    for (int i = 0; i < n_in; i++) {
        int s = in_sizes[i];
        if (s == M_TOTAL * DIN)             x = (const float*)d_in[i];           // 67108864
        else if (s == LEVELS * DOUT * DIN)  weight_bank = (const float*)d_in[i]; // 458752
        else if (s == DOUT)                 bias = (const float*)d_in[i];        // 256
        else if (s == PN)                   abits = d_in[i];                     // 8
    }

    float* out = (float*)d_out;

    cudaFuncSetAttribute(mpl_kernel, cudaFuncAttributeMaxDynamicSharedMemorySize, SMEM_BYTES);

    mpl_prep<<<(LEVELS * DOUT * DIN + 255) / 256, 256>>>(weight_bank, abits);
    mpl_kernel<<<GRID, NTHREADS, SMEM_BYTES>>>(x, bias, out);
}

// round 7
// speedup vs baseline: 1.0094x; 1.0094x over previous
#include <cuda_runtime.h>
#include <cuda_fp16.h>
#include <cstdint>

// ---------------- problem constants ----------------
#define PN         8
#define SEQ        4096
#define DIN        256
#define DOUT       256
#define LEVELS     7
#define TILE_M     64
#define KCH        64
#define NCHUNK     (DIN / KCH)          // 4
#define NTHREADS   256
#define M_PER_PATH 32768                // bpp * SEQ
#define M_TOTAL    (PN * M_PER_PATH)    // 262144
#define GRID       (M_TOTAL / TILE_M)   // 4096

// ---------------- device scratch (globals: no allocs) ----------------
__device__ __align__(16) __half g_w[LEVELS * DOUT * DIN];
__device__ int g_levels[PN];

// ---------------- smem layout (bytes) ----------------
#define A_OFF      0                    // 64 x 64 fp16  = 8 KB
#define B_OFF      8192                 // 256 x 64 fp16 = 32 KB
#define BUF_BYTES  40960                // 40 KB per stage
#define SMEM_BYTES (2 * BUF_BYTES)      // 80 KB -> 2 CTAs/SM

#define SWZ(o) ((o) ^ (((o) >> 3) & 0x70))

// ---------------- helpers ----------------
static __device__ __forceinline__ uint32_t smem_u32(const void* p) {
    uint32_t a;
    asm("{ .reg .u64 t; cvta.to.shared.u64 t, %1; cvt.u32.u64 %0, t; }" : "=r"(a) : "l"(p));
    return a;
}

static __device__ __forceinline__ void cp16(uint32_t dst, const void* src) {
    asm volatile("cp.async.cg.shared.global [%0], [%1], 16;" :: "r"(dst), "l"(src) : "memory");
}
#define CP_COMMIT() asm volatile("cp.async.commit_group;" ::: "memory")
#define CP_WAIT0()  asm volatile("cp.async.wait_group 0;" ::: "memory")

static __device__ __forceinline__ void ldsm4(uint32_t* r, uint32_t addr) {
    asm volatile("ldmatrix.sync.aligned.m8n8.x4.shared.b16 {%0,%1,%2,%3}, [%4];"
                 : "=r"(r[0]), "=r"(r[1]), "=r"(r[2]), "=r"(r[3]) : "r"(addr));
}

static __device__ __forceinline__ void mma16816(float* d, const uint32_t* a, const uint32_t* b) {
    asm volatile(
        "mma.sync.aligned.m16n8k16.row.col.f32.f16.f16.f32 "
        "{%0,%1,%2,%3}, {%4,%5,%6,%7}, {%8,%9}, {%0,%1,%2,%3};"
        : "+f"(d[0]), "+f"(d[1]), "+f"(d[2]), "+f"(d[3])
        : "r"(a[0]), "r"(a[1]), "r"(a[2]), "r"(a[3]), "r"(b[0]), "r"(b[1]));
}

static __device__ __forceinline__ uint32_t pack_h2(float f0, float f1) {
    __half2 h = __floats2half2_rn(f0, f1);
    return *reinterpret_cast<uint32_t*>(&h);
}

// ---------------- prep pass: fp32 -> fp16 weights + assigned_bits dtype fix ----------------
__global__ void mpl_prep(const float* __restrict__ w, const void* __restrict__ abits) {
    int i = blockIdx.x * 256 + threadIdx.x;
    if (i < LEVELS * DOUT * DIN)
        g_w[i] = __float2half_rn(w[i]);
    if (blockIdx.x == 0 && threadIdx.x == 0) {
        const long long* p64 = (const long long*)abits;
        const int* p32 = (const int*)abits;
        bool is64 = true;
        #pragma unroll
        for (int p = 0; p < PN; p++) {
            long long v = p64[p];
            if (v < 0 || v >= LEVELS) is64 = false;
        }
        #pragma unroll
        for (int p = 0; p < PN; p++) {
            int lv = is64 ? (int)p64[p] : p32[p];
            if (lv < 0) lv = 0;
            if (lv >= LEVELS) lv = LEVELS - 1;
            g_levels[p] = lv;
        }
    }
}

// ---------------- main GEMM: 64M x 256N tile, 256 thr, 2 CTAs/SM ----------------
__global__ void __launch_bounds__(NTHREADS, 2)
mpl_kernel(const float* __restrict__ x, const float* __restrict__ bias,
           float* __restrict__ out)
{
    extern __shared__ char smem[];
    const uint32_t sb = smem_u32(smem);
    const int tid = threadIdx.x;
    const int wid = tid >> 5;
    const int lid = tid & 31;
    const int m0 = blockIdx.x * TILE_M;
    const int path = m0 / M_PER_PATH;
    const int level = g_levels[path];

    const float* xbase = x + (size_t)m0 * DIN;
    const __half* wb = g_w + (size_t)level * DOUT * DIN;

    // warp grid: 2(M) x 4(N); warp tile 32(M) x 64(N)
    const int mrow0 = (wid >> 2) * 32;
    const int ncol0 = (wid & 3) * 64;

    // per-lane ldmatrix address components
    const int g = lid >> 3;               // matrix group 0..3
    const int lr = lid & 7;               // row within matrix
    const int a_row = (g & 1) * 8 + lr;   // A: m,(m+8),m,(m+8)
    const int a_kb  = (g >> 1) * 16;      //    k,  k,  k+8, k+8 (bytes)
    const int b_row = (g >> 1) * 8 + lr;  // B: n,  n,  n+8, n+8
    const int b_kb  = (g & 1) * 16;       //    k, k+8,  k,  k+8 (bytes)

    float4 av[4];
    // ---------- prologue: fill buffer 0 with chunk 0 ----------
    {
        #pragma unroll
        for (int i = 0; i < 4; i++) {
            int idx = tid + i * NTHREADS;      // 0..1023 : A 64 rows x 16 float4
            int r = idx >> 4, cg = idx & 15;
            av[i] = *(const float4*)(xbase + (size_t)r * DIN + cg * 4);
        }
        #pragma unroll
        for (int i = 0; i < 8; i++) {
            int idx = tid + i * NTHREADS;      // 0..2047 : B 256 rows x 8 uint4
            int n = idx >> 3, c8 = idx & 7;
            uint32_t sw = SWZ((uint32_t)(n * 128 + c8 * 16));
            cp16(sb + B_OFF + sw, wb + (size_t)n * DIN + c8 * 8);
        }
        CP_COMMIT();
        #pragma unroll
        for (int i = 0; i < 4; i++) {
            int idx = tid + i * NTHREADS;
            int r = idx >> 4, cg = idx & 15;
            uint32_t sw = SWZ((uint32_t)(r * 128 + cg * 8));
            *(uint2*)(smem + A_OFF + sw) =
                make_uint2(pack_h2(av[i].x, av[i].y), pack_h2(av[i].z, av[i].w));
        }
        CP_WAIT0();
        __syncthreads();
    }

    float acc[2][8][4];
    #pragma unroll
    for (int mt = 0; mt < 2; mt++)
        #pragma unroll
        for (int nt = 0; nt < 8; nt++)
            #pragma unroll
            for (int e = 0; e < 4; e++) acc[mt][nt][e] = 0.0f;

    // ---------- main loop over K chunks ----------
    #pragma unroll
    for (int kc = 0; kc < NCHUNK; kc++) {
        const uint32_t bufb = sb + (kc & 1) * BUF_BYTES;
        const uint32_t nbufb = sb + ((kc + 1) & 1) * BUF_BYTES;

        // prefetch next chunk: cp.async B, LDG A into regs (overlap with compute)
        if (kc < NCHUNK - 1) {
            const int kn = kc + 1;
            #pragma unroll
            for (int i = 0; i < 8; i++) {
                int idx = tid + i * NTHREADS;
                int n = idx >> 3, c8 = idx & 7;
                uint32_t sw = SWZ((uint32_t)(n * 128 + c8 * 16));
                cp16(nbufb + B_OFF + sw, wb + (size_t)n * DIN + kn * KCH + c8 * 8);
            }
            CP_COMMIT();
            #pragma unroll
            for (int i = 0; i < 4; i++) {
                int idx = tid + i * NTHREADS;
                int r = idx >> 4, cg = idx & 15;
                av[i] = *(const float4*)(xbase + (size_t)r * DIN + kn * KCH + cg * 4);
            }
        }

        // ---- compute current chunk: 4 k-steps ----
        const uint32_t abase = bufb + A_OFF;
        const uint32_t bbase = bufb + B_OFF;
        #pragma unroll
        for (int ks = 0; ks < 4; ks++) {
            uint32_t af[2][4];
            #pragma unroll
            for (int mt = 0; mt < 2; mt++) {
                uint32_t byte = (uint32_t)((mrow0 + mt * 16 + a_row) * 128 + ks * 32 + a_kb);
                ldsm4(af[mt], abase + SWZ(byte));
            }
            uint32_t bf[4][4];
            #pragma unroll
            for (int p = 0; p < 4; p++) {
                uint32_t byte = (uint32_t)((ncol0 + p * 16 + b_row) * 128 + ks * 32 + b_kb);
                ldsm4(bf[p], bbase + SWZ(byte));
            }
            #pragma unroll
            for (int mt = 0; mt < 2; mt++)
                #pragma unroll
                for (int p = 0; p < 4; p++) {
                    mma16816(acc[mt][2 * p + 0], af[mt], &bf[p][0]);
                    mma16816(acc[mt][2 * p + 1], af[mt], &bf[p][2]);
                }
        }

        // ---- stage next chunk's A; close pipeline stage ----
        if (kc < NCHUNK - 1) {
            #pragma unroll
            for (int i = 0; i < 4; i++) {
                int idx = tid + i * NTHREADS;
                int r = idx >> 4, cg = idx & 15;
                uint32_t sw = SWZ((uint32_t)(r * 128 + cg * 8));
                *(uint2*)(smem + ((kc + 1) & 1) * BUF_BYTES + A_OFF + sw) =
                    make_uint2(pack_h2(av[i].x, av[i].y), pack_h2(av[i].z, av[i].w));
            }
            CP_WAIT0();
            __syncthreads();
        }
    }

    // ---------- epilogue: bias + direct coalesced stores ----------
    const int qrow = lid >> 2;            // 0..7
    const int qcol = (lid & 3) * 2;       // 0,2,4,6
    float2 bv[8];
    #pragma unroll
    for (int nt = 0; nt < 8; nt++)
        bv[nt] = *(const float2*)(bias + ncol0 + nt * 8 + qcol);

    float* op = out + (size_t)m0 * DOUT;
    #pragma unroll
    for (int mt = 0; mt < 2; mt++) {
        int r0 = mrow0 + mt * 16 + qrow;
        #pragma unroll
        for (int nt = 0; nt < 8; nt++) {
            int c = ncol0 + nt * 8 + qcol;
            float2 v0, v1;
            v0.x = acc[mt][nt][0] + bv[nt].x;
            v0.y = acc[mt][nt][1] + bv[nt].y;
            v1.x = acc[mt][nt][2] + bv[nt].x;
            v1.y = acc[mt][nt][3] + bv[nt].y;
            *(float2*)(op + (size_t)r0 * DOUT + c) = v0;
            *(float2*)(op + (size_t)(r0 + 8) * DOUT + c) = v1;
        }
    }
}

// ---------------- launch: identify inputs BY ELEMENT COUNT (order-proof) ----------------
extern "C" void kernel_launch(void* const* d_in, const int* in_sizes, int n_in,
                              void* d_out, int out_size) {
    const float* x = nullptr;
    const float* weight_bank = nullptr;
    const float* bias = nullptr;
    const void* abits = nullptr;

    for (int i = 0; i < n_in; i++) {
        int s = in_sizes[i];
        if (s == M_TOTAL * DIN)             x = (const float*)d_in[i];           // 67108864
        else if (s == LEVELS * DOUT * DIN)  weight_bank = (const float*)d_in[i]; // 458752
        else if (s == DOUT)                 bias = (const float*)d_in[i];        // 256
        else if (s == PN)                   abits = d_in[i];                     // 8
    }

    float* out = (float*)d_out;

    cudaFuncSetAttribute(mpl_kernel, cudaFuncAttributeMaxDynamicSharedMemorySize, SMEM_BYTES);

    mpl_prep<<<(LEVELS * DOUT * DIN + 255) / 256, 256>>>(weight_bank, abits);
    mpl_kernel<<<GRID, NTHREADS, SMEM_BYTES>>>(x, bias, out);
}

// round 8
// speedup vs baseline: 1.0488x; 1.0390x over previous
#include <cuda_runtime.h>
#include <cuda_fp16.h>
#include <cstdint>

// ---------------- problem constants ----------------
#define PN         8
#define SEQ        4096
#define DIN        256
#define DOUT       256
#define LEVELS     7
#define TILE_M     128
#define NTHREADS   512
#define M_PER_PATH 32768                // bpp * SEQ
#define M_TOTAL    (PN * M_PER_PATH)    // 262144
#define GRID       (M_TOTAL / TILE_M)   // 2048

// ---------------- device scratch (globals: no allocs) ----------------
__device__ __align__(16) __half g_w[LEVELS * DOUT * DIN];
__device__ int g_levels[PN];

// ---------------- smem layout (bytes) ----------------
// Single stage holding ALL of K=256, segmented into 4 x 64-col SW128 tiles.
#define A_OFF       0                   // 4 segs x (128 x 64 fp16 = 16 KB) = 64 KB
#define A_SEG       16384
#define B_OFF       65536               // 4 segs x (256 x 64 fp16 = 32 KB) = 128 KB
#define B_SEG       32768
#define SMEM_BYTES  196608              // 192 KB

#define SWZ(o) ((o) ^ (((o) >> 3) & 0x70))

// ---------------- helpers ----------------
static __device__ __forceinline__ uint32_t smem_u32(const void* p) {
    uint32_t a;
    asm("{ .reg .u64 t; cvta.to.shared.u64 t, %1; cvt.u32.u64 %0, t; }" : "=r"(a) : "l"(p));
    return a;
}

static __device__ __forceinline__ void cp16(uint32_t dst, const void* src) {
    asm volatile("cp.async.cg.shared.global [%0], [%1], 16;" :: "r"(dst), "l"(src) : "memory");
}
#define CP_COMMIT() asm volatile("cp.async.commit_group;" ::: "memory")
#define CP_WAIT0()  asm volatile("cp.async.wait_group 0;" ::: "memory")

static __device__ __forceinline__ void ldsm4(uint32_t* r, uint32_t addr) {
    asm volatile("ldmatrix.sync.aligned.m8n8.x4.shared.b16 {%0,%1,%2,%3}, [%4];"
                 : "=r"(r[0]), "=r"(r[1]), "=r"(r[2]), "=r"(r[3]) : "r"(addr));
}

static __device__ __forceinline__ void mma16816(float* d, const uint32_t* a, const uint32_t* b) {
    asm volatile(
        "mma.sync.aligned.m16n8k16.row.col.f32.f16.f16.f32 "
        "{%0,%1,%2,%3}, {%4,%5,%6,%7}, {%8,%9}, {%0,%1,%2,%3};"
        : "+f"(d[0]), "+f"(d[1]), "+f"(d[2]), "+f"(d[3])
        : "r"(a[0]), "r"(a[1]), "r"(a[2]), "r"(a[3]), "r"(b[0]), "r"(b[1]));
}

static __device__ __forceinline__ uint32_t pack_h2(float f0, float f1) {
    __half2 h = __floats2half2_rn(f0, f1);
    return *reinterpret_cast<uint32_t*>(&h);
}

// ---------------- prep pass: fp32 -> fp16 weights + assigned_bits dtype fix ----------------
__global__ void mpl_prep(const float* __restrict__ w, const void* __restrict__ abits) {
    int i = blockIdx.x * 256 + threadIdx.x;
    if (i < LEVELS * DOUT * DIN)
        g_w[i] = __float2half_rn(w[i]);
    if (blockIdx.x == 0 && threadIdx.x == 0) {
        const long long* p64 = (const long long*)abits;
        const int* p32 = (const int*)abits;
        bool is64 = true;
        #pragma unroll
        for (int p = 0; p < PN; p++) {
            long long v = p64[p];
            if (v < 0 || v >= LEVELS) is64 = false;
        }
        #pragma unroll
        for (int p = 0; p < PN; p++) {
            int lv = is64 ? (int)p64[p] : p32[p];
            if (lv < 0) lv = 0;
            if (lv >= LEVELS) lv = LEVELS - 1;
            g_levels[p] = lv;
        }
    }
}

// ---------------- main GEMM: single-stage K=256, 512 threads, zero mid-loop barriers ----------------
__global__ void __launch_bounds__(NTHREADS, 1)
mpl_kernel(const float* __restrict__ x, const float* __restrict__ bias,
           float* __restrict__ out)
{
    extern __shared__ char smem[];
    const uint32_t sb = smem_u32(smem);
    const int tid = threadIdx.x;
    const int wid = tid >> 5;
    const int lid = tid & 31;
    const int m0 = blockIdx.x * TILE_M;
    const int path = m0 / M_PER_PATH;
    const int level = g_levels[path];

    const float* xbase = x + (size_t)m0 * DIN;
    const __half* wb = g_w + (size_t)level * DOUT * DIN;

    // warp grid: 2(M) x 8(N); warp tile 64(M) x 32(N)
    const int mrow0 = (wid >> 3) * 64;
    const int ncol0 = (wid & 7) * 32;

    // per-lane ldmatrix address components
    const int g = lid >> 3;               // matrix group 0..3
    const int lr = lid & 7;               // row within matrix
    const int a_row = (g & 1) * 8 + lr;   // A: m,(m+8),m,(m+8)
    const int a_kb  = (g >> 1) * 16;      //    k,  k,  k+8, k+8 (bytes)
    const int b_row = (g >> 1) * 8 + lr;  // B: n,  n,  n+8, n+8
    const int b_kb  = (g & 1) * 16;       //    k, k+8,  k,  k+8 (bytes)

    // ---------- prologue: load ALL of K=256 in one shot ----------
    // B first (cp.async, one commit group, high MLP, mostly L2 hits)
    #pragma unroll
    for (int seg = 0; seg < 4; seg++) {
        #pragma unroll
        for (int i = 0; i < 4; i++) {
            int idx = tid + i * NTHREADS;      // 0..2047 : 256 rows x 8 uint4
            int n = idx >> 3, c8 = idx & 7;
            uint32_t sw = SWZ((uint32_t)(n * 128 + c8 * 16));
            cp16(sb + B_OFF + seg * B_SEG + sw,
                 wb + (size_t)n * DIN + seg * 64 + c8 * 8);
        }
    }
    CP_COMMIT();

    // A: LDG fp32 -> cvt fp16 -> STS, register double-buffered across segments
    {
        float4 cur[4], nxt[4];
        #pragma unroll
        for (int i = 0; i < 4; i++) {
            int idx = tid + i * NTHREADS;      // 0..2047 : 128 rows x 16 float4
            int r = idx >> 4, cg = idx & 15;
            cur[i] = *(const float4*)(xbase + (size_t)r * DIN + cg * 4);
        }
        #pragma unroll
        for (int seg = 0; seg < 4; seg++) {
            if (seg < 3) {
                #pragma unroll
                for (int i = 0; i < 4; i++) {
                    int idx = tid + i * NTHREADS;
                    int r = idx >> 4, cg = idx & 15;
                    nxt[i] = *(const float4*)(xbase + (size_t)r * DIN + (seg + 1) * 64 + cg * 4);
                }
            }
            #pragma unroll
            for (int i = 0; i < 4; i++) {
                int idx = tid + i * NTHREADS;
                int r = idx >> 4, cg = idx & 15;
                uint32_t sw = SWZ((uint32_t)(r * 128 + cg * 8));
                *(uint2*)(smem + A_OFF + seg * A_SEG + sw) =
                    make_uint2(pack_h2(cur[i].x, cur[i].y), pack_h2(cur[i].z, cur[i].w));
            }
            #pragma unroll
            for (int i = 0; i < 4; i++) cur[i] = nxt[i];
        }
    }

    CP_WAIT0();
    __syncthreads();          // the ONLY pre-compute barrier

    // ---------- compute: 16 k-steps, zero synchronization ----------
    float acc[4][4][4];
    #pragma unroll
    for (int mt = 0; mt < 4; mt++)
        #pragma unroll
        for (int nt = 0; nt < 4; nt++)
            #pragma unroll
            for (int e = 0; e < 4; e++) acc[mt][nt][e] = 0.0f;

    #pragma unroll
    for (int ks = 0; ks < 16; ks++) {
        const int seg = ks >> 2;
        const int k4 = ks & 3;
        const uint32_t abase = sb + A_OFF + seg * A_SEG;
        const uint32_t bbase = sb + B_OFF + seg * B_SEG;

        uint32_t af[4][4];
        #pragma unroll
        for (int mt = 0; mt < 4; mt++) {
            uint32_t byte = (uint32_t)((mrow0 + mt * 16 + a_row) * 128 + k4 * 32 + a_kb);
            ldsm4(af[mt], abase + SWZ(byte));
        }
        uint32_t bf[2][4];
        #pragma unroll
        for (int p = 0; p < 2; p++) {
            uint32_t byte = (uint32_t)((ncol0 + p * 16 + b_row) * 128 + k4 * 32 + b_kb);
            ldsm4(bf[p], bbase + SWZ(byte));
        }
        #pragma unroll
        for (int mt = 0; mt < 4; mt++)
            #pragma unroll
            for (int p = 0; p < 2; p++) {
                mma16816(acc[mt][2 * p + 0], af[mt], &bf[p][0]);
                mma16816(acc[mt][2 * p + 1], af[mt], &bf[p][2]);
            }
    }

    // ---------- epilogue: bias + direct coalesced stores ----------
    const int qrow = lid >> 2;            // 0..7
    const int qcol = (lid & 3) * 2;       // 0,2,4,6
    float2 bv[4];
    #pragma unroll
    for (int nt = 0; nt < 4; nt++)
        bv[nt] = *(const float2*)(bias + ncol0 + nt * 8 + qcol);

    float* op = out + (size_t)m0 * DOUT;
    #pragma unroll
    for (int mt = 0; mt < 4; mt++) {
        int r0 = mrow0 + mt * 16 + qrow;
        #pragma unroll
        for (int nt = 0; nt < 4; nt++) {
            int c = ncol0 + nt * 8 + qcol;
            float2 v0, v1;
            v0.x = acc[mt][nt][0] + bv[nt].x;
            v0.y = acc[mt][nt][1] + bv[nt].y;
            v1.x = acc[mt][nt][2] + bv[nt].x;
            v1.y = acc[mt][nt][3] + bv[nt].y;
            *(float2*)(op + (size_t)r0 * DOUT + c) = v0;
            *(float2*)(op + (size_t)(r0 + 8) * DOUT + c) = v1;
        }
    }
}

// ---------------- launch: identify inputs BY ELEMENT COUNT (order-proof) ----------------
extern "C" void kernel_launch(void* const* d_in, const int* in_sizes, int n_in,
                              void* d_out, int out_size) {
    const float* x = nullptr;
    const float* weight_bank = nullptr;
    const float* bias = nullptr;
    const void* abits = nullptr;

    for (int i = 0; i < n_in; i++) {
        int s = in_sizes[i];
        if (s == M_TOTAL * DIN)             x = (const float*)d_in[i];           // 67108864
        else if (s == LEVELS * DOUT * DIN)  weight_bank = (const float*)d_in[i]; // 458752
        else if (s == DOUT)                 bias = (const float*)d_in[i];        // 256
        else if (s == PN)                   abits = d_in[i];                     // 8
    }

    float* out = (float*)d_out;

    cudaFuncSetAttribute(mpl_kernel, cudaFuncAttributeMaxDynamicSharedMemorySize, SMEM_BYTES);

    mpl_prep<<<(LEVELS * DOUT * DIN + 255) / 256, 256>>>(weight_bank, abits);
    mpl_kernel<<<GRID, NTHREADS, SMEM_BYTES>>>(x, bias, out);
}

// round 10
// speedup vs baseline: 1.0646x; 1.0150x over previous
#include <cuda_runtime.h>
#include <cuda_fp16.h>
#include <cstdint>

// ---------------- problem constants ----------------
#define PN         8
#define SEQ        4096
#define DIN        256
#define DOUT       256
#define LEVELS     7
#define TILE_M     64
#define NTHREADS   256
#define M_PER_PATH 32768
#define M_TOTAL    (PN * M_PER_PATH)    // 262144
#define NTILES     (M_TOTAL / TILE_M)   // 4096
#define NCTA       148                  // persistent: one CTA per SM, single wave

// ---------------- device scratch (globals: no allocs) ----------------
__device__ __align__(16) __half g_w[LEVELS * DOUT * DIN];
__device__ int g_levels[PN];

// ---------------- smem layout (bytes) ----------------
// A: two buffers of 64rows x 256K fp16 = 32 KB each (4 segs x 8 KB, SW128)
// B: resident 256n x 256K fp16 = 128 KB (4 segs x 32 KB, SW128)
#define ABUF0      0
#define ABUF1      32768
#define A_SEG      8192
#define B_OFF      65536
#define B_SEG      32768
#define SMEM_BYTES 196608               // 192 KB

#define SWZ(o) ((o) ^ (((o) >> 3) & 0x70))

// ---------------- helpers ----------------
static __device__ __forceinline__ uint32_t smem_u32(const void* p) {
    uint32_t a;
    asm("{ .reg .u64 t; cvta.to.shared.u64 t, %1; cvt.u32.u64 %0, t; }" : "=r"(a) : "l"(p));
    return a;
}

static __device__ __forceinline__ void cp16(uint32_t dst, const void* src) {
    asm volatile("cp.async.cg.shared.global [%0], [%1], 16;" :: "r"(dst), "l"(src) : "memory");
}
#define CP_COMMIT() asm volatile("cp.async.commit_group;" ::: "memory")
#define CP_WAIT0()  asm volatile("cp.async.wait_group 0;" ::: "memory")

static __device__ __forceinline__ void ldsm4(uint32_t* r, uint32_t addr) {
    asm volatile("ldmatrix.sync.aligned.m8n8.x4.shared.b16 {%0,%1,%2,%3}, [%4];"
                 : "=r"(r[0]), "=r"(r[1]), "=r"(r[2]), "=r"(r[3]) : "r"(addr));
}

static __device__ __forceinline__ void mma16816(float* d, const uint32_t* a, const uint32_t* b) {
    asm volatile(
        "mma.sync.aligned.m16n8k16.row.col.f32.f16.f16.f32 "
        "{%0,%1,%2,%3}, {%4,%5,%6,%7}, {%8,%9}, {%0,%1,%2,%3};"
        : "+f"(d[0]), "+f"(d[1]), "+f"(d[2]), "+f"(d[3])
        : "r"(a[0]), "r"(a[1]), "r"(a[2]), "r"(a[3]), "r"(b[0]), "r"(b[1]));
}

static __device__ __forceinline__ uint32_t pack_h2(float f0, float f1) {
    __half2 h = __floats2half2_rn(f0, f1);
    return *reinterpret_cast<uint32_t*>(&h);
}

// ---------------- prep pass: fp32 -> fp16 weights + assigned_bits dtype fix ----------------
__global__ void mpl_prep(const float* __restrict__ w, const void* __restrict__ abits) {
    int i = blockIdx.x * 256 + threadIdx.x;
    if (i < LEVELS * DOUT * DIN)
        g_w[i] = __float2half_rn(w[i]);
    if (blockIdx.x == 0 && threadIdx.x == 0) {
        const long long* p64 = (const long long*)abits;
        const int* p32 = (const int*)abits;
        bool is64 = true;
        #pragma unroll
        for (int p = 0; p < PN; p++) {
            long long v = p64[p];
            if (v < 0 || v >= LEVELS) is64 = false;
        }
        #pragma unroll
        for (int p = 0; p < PN; p++) {
            int lv = is64 ? (int)p64[p] : p32[p];
            if (lv < 0) lv = 0;
            if (lv >= LEVELS) lv = LEVELS - 1;
            g_levels[p] = lv;
        }
    }
}

// issue cp.async for the full resident B tile of one level (one commit group outside)
static __device__ __forceinline__ void load_B(uint32_t sb, const __half* wlvl, int tid) {
    #pragma unroll
    for (int seg = 0; seg < 4; seg++) {
        #pragma unroll
        for (int j = 0; j < 8; j++) {
            int idx = tid + j * NTHREADS;      // 0..2047: 256 rows x 8 uint4
            int n = idx >> 3, c8 = idx & 7;
            uint32_t sw = SWZ((uint32_t)(n * 128 + c8 * 16));
            cp16(sb + B_OFF + seg * B_SEG + sw,
                 wlvl + (size_t)n * DIN + seg * 64 + c8 * 8);
        }
    }
}

// ---------------- persistent GEMM: resident B, double-buffered A ----------------
__global__ void __launch_bounds__(NTHREADS, 1)
mpl_kernel(const float* __restrict__ x, const float* __restrict__ bias,
           float* __restrict__ out)
{
    extern __shared__ char smem[];
    const uint32_t sb = smem_u32(smem);
    const int tid = threadIdx.x;
    const int wid = tid >> 5;
    const int lid = tid & 31;

    // my contiguous tile range
    const int t0 = (int)(((long long)blockIdx.x * NTILES) / NCTA);
    const int t1 = (int)(((long long)(blockIdx.x + 1) * NTILES) / NCTA);

    // warp grid: 2(M) x 4(N); warp tile 32(M) x 64(N)
    const int mrow0 = (wid >> 2) * 32;
    const int ncol0 = (wid & 3) * 64;

    // per-lane ldmatrix address components
    const int g = lid >> 3;
    const int lr = lid & 7;
    const int a_row = (g & 1) * 8 + lr;
    const int a_kb  = (g >> 1) * 16;
    const int b_row = (g >> 1) * 8 + lr;
    const int b_kb  = (g & 1) * 16;

    // bias fragments (fixed per warp)
    const int qrow = lid >> 2;
    const int qcol = (lid & 3) * 2;
    float2 bv[8];
    #pragma unroll
    for (int nt = 0; nt < 8; nt++)
        bv[nt] = *(const float2*)(bias + ncol0 + nt * 8 + qcol);

    // ---------- prologue: B(level of t0) + A(t0) -> buf0 ----------
    int curlevel = g_levels[t0 >> 9];           // 512 tiles per path
    load_B(sb, g_w + (size_t)curlevel * DOUT * DIN, tid);
    CP_COMMIT();
    {
        const float* xt = x + (size_t)t0 * TILE_M * DIN;
        #pragma unroll
        for (int i = 0; i < 16; i++) {
            int idx = tid + i * NTHREADS;       // 0..4095: 64 rows x 64 float4
            int r = idx >> 6, c = idx & 63;
            float4 v = *(const float4*)(xt + (size_t)r * DIN + c * 4);
            int seg = c >> 4;
            uint32_t sw = SWZ((uint32_t)(r * 128 + (c & 15) * 8));
            *(uint2*)(smem + ABUF0 + seg * A_SEG + sw) =
                make_uint2(pack_h2(v.x, v.y), pack_h2(v.z, v.w));
        }
    }
    CP_WAIT0();
    __syncthreads();

    // ---------- persistent tile loop ----------
    for (int t = t0; t < t1; t++) {
        const uint32_t abuf = sb + ((t - t0) & 1) * ABUF1;
        const bool pf = (t + 1 < t1);

        // prefetch next tile's A rows (LDG; latency covered by ksteps 0-1)
        float4 tmp[16];
        if (pf) {
            const float* xt = x + (size_t)(t + 1) * TILE_M * DIN;
            #pragma unroll
            for (int i = 0; i < 16; i++) {
                int idx = tid + i * NTHREADS;
                int r = idx >> 6, c = idx & 63;
                tmp[i] = *(const float4*)(xt + (size_t)r * DIN + c * 4);
            }
        }

        float acc[2][8][4];
        #pragma unroll
        for (int mt = 0; mt < 2; mt++)
            #pragma unroll
            for (int nt = 0; nt < 8; nt++)
                #pragma unroll
                for (int e = 0; e < 4; e++) acc[mt][nt][e] = 0.0f;

        uint2 packed[16];

        #pragma unroll
        for (int ks = 0; ks < 16; ks++) {
            // after 2 k-steps the prefetch LDGs have landed: convert now
            if (ks == 2 && pf) {
                #pragma unroll
                for (int i = 0; i < 16; i++)
                    packed[i] = make_uint2(pack_h2(tmp[i].x, tmp[i].y),
                                           pack_h2(tmp[i].z, tmp[i].w));
            }
            const int seg = ks >> 2;
            const int k4 = ks & 3;
            const uint32_t abase = abuf + seg * A_SEG;
            const uint32_t bbase = sb + B_OFF + seg * B_SEG;

            uint32_t af[2][4];
            #pragma unroll
            for (int mt = 0; mt < 2; mt++) {
                uint32_t byte = (uint32_t)((mrow0 + mt * 16 + a_row) * 128 + k4 * 32 + a_kb);
                ldsm4(af[mt], abase + SWZ(byte));
            }
            uint32_t bf[4][4];
            #pragma unroll
            for (int p = 0; p < 4; p++) {
                uint32_t byte = (uint32_t)((ncol0 + p * 16 + b_row) * 128 + k4 * 32 + b_kb);
                ldsm4(bf[p], bbase + SWZ(byte));
            }
            #pragma unroll
            for (int mt = 0; mt < 2; mt++)
                #pragma unroll
                for (int p = 0; p < 4; p++) {
                    mma16816(acc[mt][2 * p + 0], af[mt], &bf[p][0]);
                    mma16816(acc[mt][2 * p + 1], af[mt], &bf[p][2]);
                }
        }

        // epilogue: bias + direct coalesced stores (overlaps other warps' compute)
        {
            float* op = out + (size_t)t * TILE_M * DOUT;
            #pragma unroll
            for (int mt = 0; mt < 2; mt++) {
                int r0 = mrow0 + mt * 16 + qrow;
                #pragma unroll
                for (int nt = 0; nt < 8; nt++) {
                    int c = ncol0 + nt * 8 + qcol;
                    float2 v0, v1;
                    v0.x = acc[mt][nt][0] + bv[nt].x;
                    v0.y = acc[mt][nt][1] + bv[nt].y;
                    v1.x = acc[mt][nt][2] + bv[nt].x;
                    v1.y = acc[mt][nt][3] + bv[nt].y;
                    *(float2*)(op + (size_t)r0 * DOUT + c) = v0;
                    *(float2*)(op + (size_t)(r0 + 8) * DOUT + c) = v1;
                }
            }
        }

        __syncthreads();   // everyone done reading A buf[(t+1)&1] (used 2 tiles ago) and B

        if (pf) {
            // stage next A into the other buffer
            const uint32_t nabuf_off = (((t + 1) - t0) & 1) * ABUF1;
            #pragma unroll
            for (int i = 0; i < 16; i++) {
                int idx = tid + i * NTHREADS;
                int r = idx >> 6, c = idx & 63;
                int seg = c >> 4;
                uint32_t sw = SWZ((uint32_t)(r * 128 + (c & 15) * 8));
                *(uint2*)(smem + nabuf_off + seg * A_SEG + sw) = packed[i];
            }
            // path boundary? reload resident B (rare: <=1 per CTA)
            int nl = g_levels[(t + 1) >> 9];
            if (nl != curlevel) {
                curlevel = nl;
                load_B(sb, g_w + (size_t)curlevel * DOUT * DIN, tid);
                CP_COMMIT();
                CP_WAIT0();
            }
        }
        __syncthreads();   // A stage (and any B reload) visible before next compute
    }
}

// ---------------- launch: identify inputs BY ELEMENT COUNT (order-proof) ----------------
extern "C" void kernel_launch(void* const* d_in, const int* in_sizes, int n_in,
                              void* d_out, int out_size) {
    const float* x = nullptr;
    const float* weight_bank = nullptr;
    const float* bias = nullptr;
    const void* abits = nullptr;

    for (int i = 0; i < n_in; i++) {
        int s = in_sizes[i];
        if (s == M_TOTAL * DIN)             x = (const float*)d_in[i];           // 67108864
        else if (s == LEVELS * DOUT * DIN)  weight_bank = (const float*)d_in[i]; // 458752
        else if (s == DOUT)                 bias = (const float*)d_in[i];        // 256
        else if (s == PN)                   abits = d_in[i];                     // 8
    }

    float* out = (float*)d_out;

    cudaFuncSetAttribute(mpl_kernel, cudaFuncAttributeMaxDynamicSharedMemorySize, SMEM_BYTES);

    mpl_prep<<<(LEVELS * DOUT * DIN + 255) / 256, 256>>>(weight_bank, abits);
    mpl_kernel<<<NCTA, NTHREADS, SMEM_BYTES>>>(x, bias, out);
}

// round 12
// speedup vs baseline: 1.0720x; 1.0070x over previous
#include <cuda_runtime.h>
#include <cuda_fp16.h>
#include <cstdint>

// ---------------- problem constants ----------------
#define PN         8
#define SEQ        4096
#define DIN        256
#define DOUT       256
#define LEVELS     7
#define TILE_M     64
#define NTHREADS   256
#define M_PER_PATH 32768
#define M_TOTAL    (PN * M_PER_PATH)    // 262144
#define NTILES     (M_TOTAL / TILE_M)   // 4096
#define NCTA       148                  // persistent: one CTA per SM

// ---------------- device scratch (globals: no allocs) ----------------
__device__ __align__(16) __half g_w[LEVELS * DOUT * DIN];
__device__ int g_levels[PN];

// ---------------- smem layout (bytes) ----------------
#define ABUF0      0                    // A buf x2: 64r x 256K fp16 = 32 KB each
#define ABUF1      32768
#define A_SEG      8192
#define B_OFF      65536                // resident B: 256n x 256K fp16 = 128 KB
#define B_SEG      32768
#define BIAS_OFF   196608               // 1 KB bias
#define SMEM_BYTES 197632

#define SWZ(o) ((o) ^ (((o) >> 3) & 0x70))

// ---------------- helpers ----------------
static __device__ __forceinline__ uint32_t smem_u32(const void* p) {
    uint32_t a;
    asm("{ .reg .u64 t; cvta.to.shared.u64 t, %1; cvt.u32.u64 %0, t; }" : "=r"(a) : "l"(p));
    return a;
}

static __device__ __forceinline__ void cp16(uint32_t dst, const void* src) {
    asm volatile("cp.async.cg.shared.global [%0], [%1], 16;" :: "r"(dst), "l"(src) : "memory");
}
#define CP_COMMIT() asm volatile("cp.async.commit_group;" ::: "memory")
#define CP_WAIT0()  asm volatile("cp.async.wait_group 0;" ::: "memory")

static __device__ __forceinline__ void ldsm4(uint32_t* r, uint32_t addr) {
    asm volatile("ldmatrix.sync.aligned.m8n8.x4.shared.b16 {%0,%1,%2,%3}, [%4];"
                 : "=r"(r[0]), "=r"(r[1]), "=r"(r[2]), "=r"(r[3]) : "r"(addr));
}

static __device__ __forceinline__ void mma16816(float* d, const uint32_t* a, const uint32_t* b) {
    asm volatile(
        "mma.sync.aligned.m16n8k16.row.col.f32.f16.f16.f32 "
        "{%0,%1,%2,%3}, {%4,%5,%6,%7}, {%8,%9}, {%0,%1,%2,%3};"
        : "+f"(d[0]), "+f"(d[1]), "+f"(d[2]), "+f"(d[3])
        : "r"(a[0]), "r"(a[1]), "r"(a[2]), "r"(a[3]), "r"(b[0]), "r"(b[1]));
}

static __device__ __forceinline__ uint32_t pack_h2(float f0, float f1) {
    __half2 h = __floats2half2_rn(f0, f1);
    return *reinterpret_cast<uint32_t*>(&h);
}

// ---------------- prep pass ----------------
__global__ void mpl_prep(const float* __restrict__ w, const void* __restrict__ abits) {
    int i = blockIdx.x * 256 + threadIdx.x;
    if (i < LEVELS * DOUT * DIN)
        g_w[i] = __float2half_rn(w[i]);
    if (blockIdx.x == 0 && threadIdx.x == 0) {
        const long long* p64 = (const long long*)abits;
        const int* p32 = (const int*)abits;
        bool is64 = true;
        #pragma unroll
        for (int p = 0; p < PN; p++) {
            long long v = p64[p];
            if (v < 0 || v >= LEVELS) is64 = false;
        }
        #pragma unroll
        for (int p = 0; p < PN; p++) {
            int lv = is64 ? (int)p64[p] : p32[p];
            if (lv < 0) lv = 0;
            if (lv >= LEVELS) lv = LEVELS - 1;
            g_levels[p] = lv;
        }
    }
}

// resident B fill (one commit group by caller)
static __device__ __forceinline__ void load_B(uint32_t sb, const __half* wlvl, int tid) {
    #pragma unroll
    for (int seg = 0; seg < 4; seg++) {
        #pragma unroll
        for (int j = 0; j < 8; j++) {
            int idx = tid + j * NTHREADS;
            int n = idx >> 3, c8 = idx & 7;
            uint32_t sw = SWZ((uint32_t)(n * 128 + c8 * 16));
            cp16(sb + B_OFF + seg * B_SEG + sw,
                 wlvl + (size_t)n * DIN + seg * 64 + c8 * 8);
        }
    }
}

// ---------------- persistent GEMM: resident B, pipelined fragments ----------------
__global__ void __launch_bounds__(NTHREADS, 1)
mpl_kernel(const float* __restrict__ x, const float* __restrict__ bias,
           float* __restrict__ out)
{
    extern __shared__ char smem[];
    const uint32_t sb = smem_u32(smem);
    const int tid = threadIdx.x;
    const int wid = tid >> 5;
    const int lid = tid & 31;

    const int t0 = (int)(((long long)blockIdx.x * NTILES) / NCTA);
    const int t1 = (int)(((long long)(blockIdx.x + 1) * NTILES) / NCTA);

    // warp grid: 2(M) x 4(N); warp tile 32(M) x 64(N)
    const int mrow0 = (wid >> 2) * 32;
    const int ncol0 = (wid & 3) * 64;

    const int g = lid >> 3;
    const int lr = lid & 7;
    const int a_row = (g & 1) * 8 + lr;
    const int a_kb  = (g >> 1) * 16;
    const int b_row = (g >> 1) * 8 + lr;
    const int b_kb  = (g & 1) * 16;

    const int qrow = lid >> 2;
    const int qcol = (lid & 3) * 2;

    // bias -> smem (frees registers)
    if (tid < 128)
        *(float2*)(smem + BIAS_OFF + tid * 8) = *(const float2*)(bias + tid * 2);

    // ---------- prologue: B(level of t0) + A(t0) -> buf0 ----------
    int curlevel = g_levels[t0 >> 9];
    load_B(sb, g_w + (size_t)curlevel * DOUT * DIN, tid);
    CP_COMMIT();
    {
        const float* xt = x + (size_t)t0 * TILE_M * DIN;
        #pragma unroll
        for (int i = 0; i < 16; i++) {
            int idx = tid + i * NTHREADS;
            int r = idx >> 6, c = idx & 63;
            float4 v = *(const float4*)(xt + (size_t)r * DIN + c * 4);
            int seg = c >> 4;
            uint32_t sw = SWZ((uint32_t)(r * 128 + (c & 15) * 8));
            *(uint2*)(smem + ABUF0 + seg * A_SEG + sw) =
                make_uint2(pack_h2(v.x, v.y), pack_h2(v.z, v.w));
        }
    }
    CP_WAIT0();
    __syncthreads();

    // ---------- persistent tile loop ----------
    for (int t = t0; t < t1; t++) {
        const uint32_t abuf = sb + ((t - t0) & 1) * ABUF1;
        const uint32_t nabuf_off = (((t + 1) - t0) & 1) * ABUF1;
        const bool pf = (t + 1 < t1);

        // prefetch next tile's A rows into registers (converted+stored at ks==2)
        float4 tmp[16];
        if (pf) {
            const float* xt = x + (size_t)(t + 1) * TILE_M * DIN;
            #pragma unroll
            for (int i = 0; i < 16; i++) {
                int idx = tid + i * NTHREADS;
                int r = idx >> 6, c = idx & 63;
                tmp[i] = *(const float4*)(xt + (size_t)r * DIN + c * 4);
            }
        }

        float acc[2][8][4];
        #pragma unroll
        for (int mt = 0; mt < 2; mt++)
            #pragma unroll
            for (int nt = 0; nt < 8; nt++)
                #pragma unroll
                for (int e = 0; e < 4; e++) acc[mt][nt][e] = 0.0f;

        // double-buffered fragments: ldsm for ks+1 overlaps HMMA of ks
        uint32_t af2[2][2][4];
        uint32_t bf2[2][4][4];

        // load ks=0 fragments
        #pragma unroll
        for (int mt = 0; mt < 2; mt++) {
            uint32_t byte = (uint32_t)((mrow0 + mt * 16 + a_row) * 128 + a_kb);
            ldsm4(af2[0][mt], abuf + SWZ(byte));
        }
        #pragma unroll
        for (int p = 0; p < 4; p++) {
            uint32_t byte = (uint32_t)((ncol0 + p * 16 + b_row) * 128 + b_kb);
            ldsm4(bf2[0][p], sb + B_OFF + SWZ(byte));
        }

        #pragma unroll
        for (int ks = 0; ks < 16; ks++) {
            const int cb = ks & 1;
            const int nb = cb ^ 1;

            // issue ldsm for ks+1 (lands while this ks's HMMAs run)
            if (ks < 15) {
                const int ks1 = ks + 1;
                const int seg1 = ks1 >> 2;
                const int k41 = ks1 & 3;
                const uint32_t abase1 = abuf + seg1 * A_SEG;
                const uint32_t bbase1 = sb + B_OFF + seg1 * B_SEG;
                #pragma unroll
                for (int mt = 0; mt < 2; mt++) {
                    uint32_t byte = (uint32_t)((mrow0 + mt * 16 + a_row) * 128 + k41 * 32 + a_kb);
                    ldsm4(af2[nb][mt], abase1 + SWZ(byte));
                }
                #pragma unroll
                for (int p = 0; p < 4; p++) {
                    uint32_t byte = (uint32_t)((ncol0 + p * 16 + b_row) * 128 + k41 * 32 + b_kb);
                    ldsm4(bf2[nb][p], bbase1 + SWZ(byte));
                }
            }

            // A prefetch landed: convert + store DIRECTLY to next buffer
            // (safe: its readers all passed the previous tile's barrier)
            if (ks == 2 && pf) {
                #pragma unroll
                for (int i = 0; i < 16; i++) {
                    int idx = tid + i * NTHREADS;
                    int r = idx >> 6, c = idx & 63;
                    int seg = c >> 4;
                    uint32_t sw = SWZ((uint32_t)(r * 128 + (c & 15) * 8));
                    *(uint2*)(smem + nabuf_off + seg * A_SEG + sw) =
                        make_uint2(pack_h2(tmp[i].x, tmp[i].y), pack_h2(tmp[i].z, tmp[i].w));
                }
            }

            // 16 HMMA on current fragments
            #pragma unroll
            for (int mt = 0; mt < 2; mt++)
                #pragma unroll
                for (int p = 0; p < 4; p++) {
                    mma16816(acc[mt][2 * p + 0], af2[cb][mt], &bf2[cb][p][0]);
                    mma16816(acc[mt][2 * p + 1], af2[cb][mt], &bf2[cb][p][2]);
                }
        }

        // epilogue: bias (from smem) + coalesced stores
        {
            float* op = out + (size_t)t * TILE_M * DOUT;
            const float* bsm = (const float*)(smem + BIAS_OFF);
            #pragma unroll
            for (int mt = 0; mt < 2; mt++) {
                int r0 = mrow0 + mt * 16 + qrow;
                #pragma unroll
                for (int nt = 0; nt < 8; nt++) {
                    int c = ncol0 + nt * 8 + qcol;
                    float2 bvv = *(const float2*)(bsm + c);
                    float2 v0, v1;
                    v0.x = acc[mt][nt][0] + bvv.x;
                    v0.y = acc[mt][nt][1] + bvv.y;
                    v1.x = acc[mt][nt][2] + bvv.x;
                    v1.y = acc[mt][nt][3] + bvv.y;
                    *(float2*)(op + (size_t)r0 * DOUT + c) = v0;
                    *(float2*)(op + (size_t)(r0 + 8) * DOUT + c) = v1;
                }
            }
        }

        // single barrier per tile: next-A STS visible, all reads of old buffer done
        __syncthreads();

        // path boundary? reload resident B (rare: <=1 per CTA)
        if (pf) {
            int nl = g_levels[(t + 1) >> 9];
            if (nl != curlevel) {
                curlevel = nl;
                load_B(sb, g_w + (size_t)curlevel * DOUT * DIN, tid);
                CP_COMMIT();
                CP_WAIT0();
                __syncthreads();
            }
        }
    }
}

// ---------------- launch: identify inputs BY ELEMENT COUNT ----------------
extern "C" void kernel_launch(void* const* d_in, const int* in_sizes, int n_in,
                              void* d_out, int out_size) {
    const float* x = nullptr;
    const float* weight_bank = nullptr;
    const float* bias = nullptr;
    const void* abits = nullptr;

    for (int i = 0; i < n_in; i++) {
        int s = in_sizes[i];
        if (s == M_TOTAL * DIN)             x = (const float*)d_in[i];
        else if (s == LEVELS * DOUT * DIN)  weight_bank = (const float*)d_in[i];
        else if (s == DOUT)                 bias = (const float*)d_in[i];
        else if (s == PN)                   abits = d_in[i];
    }

    float* out = (float*)d_out;

    cudaFuncSetAttribute(mpl_kernel, cudaFuncAttributeMaxDynamicSharedMemorySize, SMEM_BYTES);

    mpl_prep<<<(LEVELS * DOUT * DIN + 255) / 256, 256>>>(weight_bank, abits);
    mpl_kernel<<<NCTA, NTHREADS, SMEM_BYTES>>>(x, bias, out);
}

// round 15
// speedup vs baseline: 1.1315x; 1.0555x over previous
#include <cuda_runtime.h>
#include <cuda_fp16.h>
#include <cstdint>

// ---------------- problem constants ----------------
#define PN         8
#define SEQ        4096
#define DIN        256
#define DOUT       256
#define LEVELS     7
#define TILE_M     64
#define NTHREADS   256
#define M_PER_PATH 32768
#define M_TOTAL    (PN * M_PER_PATH)    // 262144
#define NTILES     (M_TOTAL / TILE_M)   // 4096
#define NCTA       148                  // persistent: one CTA per SM

// ---------------- device scratch (globals: no allocs) ----------------
__device__ __align__(16) __half g_w[LEVELS * DOUT * DIN];
__device__ int g_levels[PN];

// ---------------- smem layout (bytes) ----------------
#define ABUF0      0                    // A buf x2: 64r x 256K fp16 = 32 KB each
#define ABUF1      32768
#define A_SEG      8192
#define B_OFF      65536                // resident B: 256n x 256K fp16 = 128 KB
#define B_SEG      32768
#define BIAS_OFF   196608               // 1 KB bias
#define SMEM_BYTES 197632

#define SWZ(o) ((o) ^ (((o) >> 3) & 0x70))

// ---------------- helpers ----------------
static __device__ __forceinline__ uint32_t smem_u32(const void* p) {
    uint32_t a;
    asm("{ .reg .u64 t; cvta.to.shared.u64 t, %1; cvt.u32.u64 %0, t; }" : "=r"(a) : "l"(p));
    return a;
}

static __device__ __forceinline__ void cp16(uint32_t dst, const void* src) {
    asm volatile("cp.async.cg.shared.global [%0], [%1], 16;" :: "r"(dst), "l"(src) : "memory");
}
#define CP_COMMIT() asm volatile("cp.async.commit_group;" ::: "memory")
#define CP_WAIT0()  asm volatile("cp.async.wait_group 0;" ::: "memory")

static __device__ __forceinline__ void ldsm4(uint32_t* r, uint32_t addr) {
    asm volatile("ldmatrix.sync.aligned.m8n8.x4.shared.b16 {%0,%1,%2,%3}, [%4];"
                 : "=r"(r[0]), "=r"(r[1]), "=r"(r[2]), "=r"(r[3]) : "r"(addr));
}

static __device__ __forceinline__ void mma16816(float* d, const uint32_t* a, const uint32_t* b) {
    asm volatile(
        "mma.sync.aligned.m16n8k16.row.col.f32.f16.f16.f32 "
        "{%0,%1,%2,%3}, {%4,%5,%6,%7}, {%8,%9}, {%0,%1,%2,%3};"
        : "+f"(d[0]), "+f"(d[1]), "+f"(d[2]), "+f"(d[3])
        : "r"(a[0]), "r"(a[1]), "r"(a[2]), "r"(a[3]), "r"(b[0]), "r"(b[1]));
}

static __device__ __forceinline__ uint32_t pack_h2(float f0, float f1) {
    __half2 h = __floats2half2_rn(f0, f1);
    return *reinterpret_cast<uint32_t*>(&h);
}

// ---------------- prep pass ----------------
__global__ void mpl_prep(const float* __restrict__ w, const void* __restrict__ abits) {
    int i = blockIdx.x * 256 + threadIdx.x;
    if (i < LEVELS * DOUT * DIN)
        g_w[i] = __float2half_rn(w[i]);
    if (blockIdx.x == 0 && threadIdx.x == 0) {
        const long long* p64 = (const long long*)abits;
        const int* p32 = (const int*)abits;
        bool is64 = true;
        #pragma unroll
        for (int p = 0; p < PN; p++) {
            long long v = p64[p];
            if (v < 0 || v >= LEVELS) is64 = false;
        }
        #pragma unroll
        for (int p = 0; p < PN; p++) {
            int lv = is64 ? (int)p64[p] : p32[p];
            if (lv < 0) lv = 0;
            if (lv >= LEVELS) lv = LEVELS - 1;
            g_levels[p] = lv;
        }
    }
}

// resident B fill (one commit group by caller)
static __device__ __forceinline__ void load_B(uint32_t sb, const __half* wlvl, int tid) {
    #pragma unroll
    for (int seg = 0; seg < 4; seg++) {
        #pragma unroll
        for (int j = 0; j < 8; j++) {
            int idx = tid + j * NTHREADS;
            int n = idx >> 3, c8 = idx & 7;
            uint32_t sw = SWZ((uint32_t)(n * 128 + c8 * 16));
            cp16(sb + B_OFF + seg * B_SEG + sw,
                 wlvl + (size_t)n * DIN + seg * 64 + c8 * 8);
        }
    }
}

// ---------------- persistent GEMM: resident B, register-lean pipelined fragments ----------------
__global__ void __launch_bounds__(NTHREADS, 1)
mpl_kernel(const float* __restrict__ x, const float* __restrict__ bias,
           float* __restrict__ out)
{
    extern __shared__ char smem[];
    const uint32_t sb = smem_u32(smem);
    const int tid = threadIdx.x;
    const int wid = tid >> 5;
    const int lid = tid & 31;

    const int t0 = (int)(((long long)blockIdx.x * NTILES) / NCTA);
    const int t1 = (int)(((long long)(blockIdx.x + 1) * NTILES) / NCTA);

    // warp grid: 2(M) x 4(N); warp tile 32(M) x 64(N)
    const int mrow0 = (wid >> 2) * 32;
    const int ncol0 = (wid & 3) * 64;

    const int g = lid >> 3;
    const int lr = lid & 7;
    const int a_row = (g & 1) * 8 + lr;
    const int a_kb  = (g >> 1) * 16;
    const int b_row = (g >> 1) * 8 + lr;
    const int b_kb  = (g & 1) * 16;

    const int qrow = lid >> 2;
    const int qcol = (lid & 3) * 2;

    // per-thread A staging indices (segment layout: 64 rows x 16 float4-cols per seg)
    const int st_r  = (tid + 0 * NTHREADS) >> 4;      // rows for i=0..3: tid>>4, +16, +32, +48
    const int st_c  = tid & 15;

    // bias -> smem (frees registers)
    if (tid < 128)
        *(float2*)(smem + BIAS_OFF + tid * 8) = *(const float2*)(bias + tid * 2);

    // ---------- prologue: B(level of t0) + A(t0) -> buf0 ----------
    int curlevel = g_levels[t0 >> 9];
    load_B(sb, g_w + (size_t)curlevel * DOUT * DIN, tid);
    CP_COMMIT();
    {
        const float* xt = x + (size_t)t0 * TILE_M * DIN;
        #pragma unroll
        for (int i = 0; i < 16; i++) {
            int idx = tid + i * NTHREADS;
            int r = idx >> 6, c = idx & 63;
            float4 v = *(const float4*)(xt + (size_t)r * DIN + c * 4);
            int seg = c >> 4;
            uint32_t sw = SWZ((uint32_t)(r * 128 + (c & 15) * 8));
            *(uint2*)(smem + ABUF0 + seg * A_SEG + sw) =
                make_uint2(pack_h2(v.x, v.y), pack_h2(v.z, v.w));
        }
    }
    CP_WAIT0();
    __syncthreads();

    // ---------- persistent tile loop ----------
    for (int t = t0; t < t1; t++) {
        const uint32_t abuf = sb + ((t - t0) & 1) * ABUF1;
        const uint32_t nabuf_off = (((t + 1) - t0) & 1) * ABUF1;
        const bool pf = (t + 1 < t1);
        const float* xnext = x + (size_t)(t + 1) * TILE_M * DIN;

        float acc[2][8][4];
        #pragma unroll
        for (int mt = 0; mt < 2; mt++)
            #pragma unroll
            for (int nt = 0; nt < 8; nt++)
                #pragma unroll
                for (int e = 0; e < 4; e++) acc[mt][nt][e] = 0.0f;

        // segmented A prefetch buffer: 16 regs total (vs 64 before)
        float4 seg[4];

        // double-buffered fragments: ldsm for ks+1 overlaps HMMA of ks
        uint32_t af2[2][2][4];
        uint32_t bf2[2][4][4];

        // load ks=0 fragments
        #pragma unroll
        for (int mt = 0; mt < 2; mt++) {
            uint32_t byte = (uint32_t)((mrow0 + mt * 16 + a_row) * 128 + a_kb);
            ldsm4(af2[0][mt], abuf + SWZ(byte));
        }
        #pragma unroll
        for (int p = 0; p < 4; p++) {
            uint32_t byte = (uint32_t)((ncol0 + p * 16 + b_row) * 128 + b_kb);
            ldsm4(bf2[0][p], sb + B_OFF + SWZ(byte));
        }

        #pragma unroll
        for (int ks = 0; ks < 16; ks++) {
            const int cb = ks & 1;
            const int nb = cb ^ 1;

            // segmented A prefetch: LDG seg s at ks==4s; convert+STS at ks==4s+3
            if (pf && (ks & 3) == 0) {
                const int s = ks >> 2;
                #pragma unroll
                for (int i = 0; i < 4; i++)
                    seg[i] = *(const float4*)(xnext + (size_t)(st_r + i * 16) * DIN
                                              + s * 64 + st_c * 4);
            }

            // issue ldsm for ks+1 (lands while this ks's HMMAs run)
            if (ks < 15) {
                const int ks1 = ks + 1;
                const int seg1 = ks1 >> 2;
                const int k41 = ks1 & 3;
                const uint32_t abase1 = abuf + seg1 * A_SEG;
                const uint32_t bbase1 = sb + B_OFF + seg1 * B_SEG;
                #pragma unroll
                for (int mt = 0; mt < 2; mt++) {
                    uint32_t byte = (uint32_t)((mrow0 + mt * 16 + a_row) * 128 + k41 * 32 + a_kb);
                    ldsm4(af2[nb][mt], abase1 + SWZ(byte));
                }
                #pragma unroll
                for (int p = 0; p < 4; p++) {
                    uint32_t byte = (uint32_t)((ncol0 + p * 16 + b_row) * 128 + k41 * 32 + b_kb);
                    ldsm4(bf2[nb][p], bbase1 + SWZ(byte));
                }
            }

            if (pf && (ks & 3) == 3) {
                const int s = ks >> 2;
                const uint32_t sdst = nabuf_off + s * A_SEG;
                const uint32_t swb = SWZ((uint32_t)(st_r * 128 + st_c * 8));
                // rows st_r, +16, +32, +48: swizzle differs only in row bits (>=128B), so add
                #pragma unroll
                for (int i = 0; i < 4; i++) {
                    *(uint2*)(smem + sdst + swb + i * 2048) =
                        make_uint2(pack_h2(seg[i].x, seg[i].y), pack_h2(seg[i].z, seg[i].w));
                }
            }

            // 16 HMMA on current fragments
            #pragma unroll
            for (int mt = 0; mt < 2; mt++)
                #pragma unroll
                for (int p = 0; p < 4; p++) {
                    mma16816(acc[mt][2 * p + 0], af2[cb][mt], &bf2[cb][p][0]);
                    mma16816(acc[mt][2 * p + 1], af2[cb][mt], &bf2[cb][p][2]);
                }
        }

        // epilogue: bias (from smem) + coalesced stores
        {
            float* op = out + (size_t)t * TILE_M * DOUT;
            const float* bsm = (const float*)(smem + BIAS_OFF);
            #pragma unroll
            for (int mt = 0; mt < 2; mt++) {
                int r0 = mrow0 + mt * 16 + qrow;
                #pragma unroll
                for (int nt = 0; nt < 8; nt++) {
                    int c = ncol0 + nt * 8 + qcol;
                    float2 bvv = *(const float2*)(bsm + c);
                    float2 v0, v1;
                    v0.x = acc[mt][nt][0] + bvv.x;
                    v0.y = acc[mt][nt][1] + bvv.y;
                    v1.x = acc[mt][nt][2] + bvv.x;
                    v1.y = acc[mt][nt][3] + bvv.y;
                    *(float2*)(op + (size_t)r0 * DOUT + c) = v0;
                    *(float2*)(op + (size_t)(r0 + 8) * DOUT + c) = v1;
                }
            }
        }

        // single barrier per tile: next-A STS visible, all reads of old buffer done
        __syncthreads();

        // path boundary? reload resident B (rare: <=1 per CTA)
        if (pf) {
            int nl = g_levels[(t + 1) >> 9];
            if (nl != curlevel) {
                curlevel = nl;
                load_B(sb, g_w + (size_t)curlevel * DOUT * DIN, tid);
                CP_COMMIT();
                CP_WAIT0();
                __syncthreads();
            }
        }
    }
}

// ---------------- launch: identify inputs BY ELEMENT COUNT ----------------
extern "C" void kernel_launch(void* const* d_in, const int* in_sizes, int n_in,
                              void* d_out, int out_size) {
    const float* x = nullptr;
    const float* weight_bank = nullptr;
    const float* bias = nullptr;
    const void* abits = nullptr;

    for (int i = 0; i < n_in; i++) {
        int s = in_sizes[i];
        if (s == M_TOTAL * DIN)             x = (const float*)d_in[i];
        else if (s == LEVELS * DOUT * DIN)  weight_bank = (const float*)d_in[i];
        else if (s == DOUT)                 bias = (const float*)d_in[i];
        else if (s == PN)                   abits = d_in[i];
    }

    float* out = (float*)d_out;

    cudaFuncSetAttribute(mpl_kernel, cudaFuncAttributeMaxDynamicSharedMemorySize, SMEM_BYTES);

    mpl_prep<<<(LEVELS * DOUT * DIN + 255) / 256, 256>>>(weight_bank, abits);
    mpl_kernel<<<NCTA, NTHREADS, SMEM_BYTES>>>(x, bias, out);
}

// round 17
// speedup vs baseline: 1.1367x; 1.0046x over previous
#include <cuda_runtime.h>
#include <cuda_fp16.h>
#include <cstdint>

// ---------------- problem constants ----------------
#define PN         8
#define SEQ        4096
#define DIN        256
#define DOUT       256
#define LEVELS     7
#define TILE_M     128
#define CHUNK      64
#define NTHREADS   256
#define M_PER_PATH 32768
#define M_TOTAL    (PN * M_PER_PATH)    // 262144
#define NTILES     (M_TOTAL / TILE_M)   // 2048
#define TPP        (M_PER_PATH / TILE_M) // 256 tiles per path
#define NCTA       148                  // persistent: one CTA per SM

// ---------------- device scratch (globals: no allocs) ----------------
__device__ __align__(16) __half g_w[LEVELS * DOUT * DIN];
__device__ int g_levels[PN];

// ---------------- smem layout (bytes) ----------------
// A: 2 chunk buffers, each 128 rows x 64 K fp16 = 16 KB (SW128, 128B rows)
// B: resident 256n x 256K fp16 = 128 KB (4 segs x 32 KB)
#define ABUF_SZ    16384
#define ABUF0      0
#define ABUF1      16384
#define B_OFF      32768
#define B_SEG      32768
#define BIAS_OFF   163840
#define SMEM_BYTES 164864               // ~161 KB

#define SWZ(o) ((o) ^ (((o) >> 3) & 0x70))

// ---------------- helpers ----------------
static __device__ __forceinline__ uint32_t smem_u32(const void* p) {
    uint32_t a;
    asm("{ .reg .u64 t; cvta.to.shared.u64 t, %1; cvt.u32.u64 %0, t; }" : "=r"(a) : "l"(p));
    return a;
}

static __device__ __forceinline__ void cp16(uint32_t dst, const void* src) {
    asm volatile("cp.async.cg.shared.global [%0], [%1], 16;" :: "r"(dst), "l"(src) : "memory");
}
#define CP_COMMIT() asm volatile("cp.async.commit_group;" ::: "memory")
#define CP_WAIT0()  asm volatile("cp.async.wait_group 0;" ::: "memory")

static __device__ __forceinline__ void ldsm4(uint32_t* r, uint32_t addr) {
    asm volatile("ldmatrix.sync.aligned.m8n8.x4.shared.b16 {%0,%1,%2,%3}, [%4];"
                 : "=r"(r[0]), "=r"(r[1]), "=r"(r[2]), "=r"(r[3]) : "r"(addr));
}

static __device__ __forceinline__ void mma16816(float* d, const uint32_t* a, const uint32_t* b) {
    asm volatile(
        "mma.sync.aligned.m16n8k16.row.col.f32.f16.f16.f32 "
        "{%0,%1,%2,%3}, {%4,%5,%6,%7}, {%8,%9}, {%0,%1,%2,%3};"
        : "+f"(d[0]), "+f"(d[1]), "+f"(d[2]), "+f"(d[3])
        : "r"(a[0]), "r"(a[1]), "r"(a[2]), "r"(a[3]), "r"(b[0]), "r"(b[1]));
}

static __device__ __forceinline__ uint32_t pack_h2(float f0, float f1) {
    __half2 h = __floats2half2_rn(f0, f1);
    return *reinterpret_cast<uint32_t*>(&h);
}

// ---------------- prep pass ----------------
__global__ void mpl_prep(const float* __restrict__ w, const void* __restrict__ abits) {
    int i = blockIdx.x * 256 + threadIdx.x;
    if (i < LEVELS * DOUT * DIN)
        g_w[i] = __float2half_rn(w[i]);
    if (blockIdx.x == 0 && threadIdx.x == 0) {
        const long long* p64 = (const long long*)abits;
        const int* p32 = (const int*)abits;
        bool is64 = true;
        #pragma unroll
        for (int p = 0; p < PN; p++) {
            long long v = p64[p];
            if (v < 0 || v >= LEVELS) is64 = false;
        }
        #pragma unroll
        for (int p = 0; p < PN; p++) {
            int lv = is64 ? (int)p64[p] : p32[p];
            if (lv < 0) lv = 0;
            if (lv >= LEVELS) lv = LEVELS - 1;
            g_levels[p] = lv;
        }
    }
}

// resident B fill (one commit group by caller)
static __device__ __forceinline__ void load_B(uint32_t sb, const __half* wlvl, int tid) {
    #pragma unroll
    for (int seg = 0; seg < 4; seg++) {
        #pragma unroll
        for (int j = 0; j < 8; j++) {
            int idx = tid + j * NTHREADS;
            int n = idx >> 3, c8 = idx & 7;
            uint32_t sw = SWZ((uint32_t)(n * 128 + c8 * 16));
            cp16(sb + B_OFF + seg * B_SEG + sw,
                 wlvl + (size_t)n * DIN + seg * 64 + c8 * 8);
        }
    }
}

// ---------------- persistent GEMM: warp 64x64, resident B, K-chunked A ----------------
__global__ void __launch_bounds__(NTHREADS, 1)
mpl_kernel(const float* __restrict__ x, const float* __restrict__ bias,
           float* __restrict__ out)
{
    extern __shared__ char smem[];
    const uint32_t sb = smem_u32(smem);
    const int tid = threadIdx.x;
    const int wid = tid >> 5;
    const int lid = tid & 31;

    const int t0 = (int)(((long long)blockIdx.x * NTILES) / NCTA);
    const int t1 = (int)(((long long)(blockIdx.x + 1) * NTILES) / NCTA);

    // warp grid: 2(M) x 4(N); warp tile 64(M) x 64(N)
    const int mrow0 = (wid >> 2) * 64;
    const int ncol0 = (wid & 3) * 64;

    const int g = lid >> 3;
    const int lr = lid & 7;
    const int a_row = (g & 1) * 8 + lr;
    const int a_kb  = (g >> 1) * 16;
    const int b_row = (g >> 1) * 8 + lr;
    const int b_kb  = (g & 1) * 16;

    const int qrow = lid >> 2;
    const int qcol = (lid & 3) * 2;

    // A staging: each thread owns col-group cg (fixed) and rows base_r+16i
    const int base_r = tid >> 4;          // 0..15
    const int cg     = tid & 15;          // float4 col within chunk
    const uint32_t stg_swz = SWZ((uint32_t)(base_r * 128 + cg * 8));
    // NOTE: + i*2048 below is safe (row deltas land in bits >=11, above the
    // swizzle mask's source bits). Fragment addresses must use full-offset SWZ.

    // bias -> smem
    if (tid < 128)
        *(float2*)(smem + BIAS_OFF + tid * 8) = *(const float2*)(bias + tid * 2);

    // ---------- prologue: B(level of t0) + A chunk0 of t0 -> buf0 ----------
    int curlevel = g_levels[t0 / TPP];
    load_B(sb, g_w + (size_t)curlevel * DOUT * DIN, tid);
    CP_COMMIT();
    {
        float4 v[8];
        const float* xt = x + (size_t)t0 * TILE_M * DIN;
        #pragma unroll
        for (int i = 0; i < 8; i++)
            v[i] = *(const float4*)(xt + (size_t)(base_r + 16 * i) * DIN + cg * 4);
        #pragma unroll
        for (int i = 0; i < 8; i++)
            *(uint2*)(smem + ABUF0 + stg_swz + i * 2048) =
                make_uint2(pack_h2(v[i].x, v[i].y), pack_h2(v[i].z, v[i].w));
    }
    CP_WAIT0();
    __syncthreads();

    // ---------- persistent tile loop ----------
    for (int t = t0; t < t1; t++) {
        float acc[4][8][4];
        #pragma unroll
        for (int mt = 0; mt < 4; mt++)
            #pragma unroll
            for (int nt = 0; nt < 8; nt++)
                #pragma unroll
                for (int e = 0; e < 4; e++) acc[mt][nt][e] = 0.0f;

        #pragma unroll
        for (int c = 0; c < 4; c++) {
            const int gidx = (t - t0) * 4 + c;
            const uint32_t abuf = sb + (gidx & 1) * ABUF_SZ;
            const uint32_t nbuf_off = ((gidx + 1) & 1) * ABUF_SZ;
            const bool has_next = (c < 3) || (t + 1 < t1);

            // prefetch next chunk's A (LDG; covered by 4 k-steps of compute)
            float4 v[8];
            if (has_next) {
                const int ntile = (c < 3) ? t : (t + 1);
                const int nch = (c + 1) & 3;
                const float* xt = x + (size_t)ntile * TILE_M * DIN + nch * CHUNK;
                #pragma unroll
                for (int i = 0; i < 8; i++)
                    v[i] = *(const float4*)(xt + (size_t)(base_r + 16 * i) * DIN + cg * 4);
            }

            // compute 4 k-steps on this chunk (full-offset swizzle: correct)
            const uint32_t bbase = sb + B_OFF + c * B_SEG;
            #pragma unroll
            for (int k4 = 0; k4 < 4; k4++) {
                uint32_t af[4][4], bf[4][4];
                #pragma unroll
                for (int mt = 0; mt < 4; mt++) {
                    uint32_t byte = (uint32_t)((mrow0 + mt * 16 + a_row) * 128 + k4 * 32 + a_kb);
                    ldsm4(af[mt], abuf + SWZ(byte));
                }
                #pragma unroll
                for (int p = 0; p < 4; p++) {
                    uint32_t byte = (uint32_t)((ncol0 + p * 16 + b_row) * 128 + k4 * 32 + b_kb);
                    ldsm4(bf[p], bbase + SWZ(byte));
                }
                #pragma unroll
                for (int mt = 0; mt < 4; mt++)
                    #pragma unroll
                    for (int p = 0; p < 4; p++) {
                        mma16816(acc[mt][2 * p + 0], af[mt], &bf[p][0]);
                        mma16816(acc[mt][2 * p + 1], af[mt], &bf[p][2]);
                    }
            }

            // stage next chunk into the other buffer
            if (has_next) {
                #pragma unroll
                for (int i = 0; i < 8; i++)
                    *(uint2*)(smem + nbuf_off + stg_swz + i * 2048) =
                        make_uint2(pack_h2(v[i].x, v[i].y), pack_h2(v[i].z, v[i].w));
            }
            __syncthreads();
        }

        // epilogue: bias (smem) + coalesced stores
        {
            float* op = out + (size_t)t * TILE_M * DOUT;
            const float* bsm = (const float*)(smem + BIAS_OFF);
            #pragma unroll
            for (int mt = 0; mt < 4; mt++) {
                int r0 = mrow0 + mt * 16 + qrow;
                #pragma unroll
                for (int nt = 0; nt < 8; nt++) {
                    int c = ncol0 + nt * 8 + qcol;
                    float2 bvv = *(const float2*)(bsm + c);
                    float2 v0, v1;
                    v0.x = acc[mt][nt][0] + bvv.x;
                    v0.y = acc[mt][nt][1] + bvv.y;
                    v1.x = acc[mt][nt][2] + bvv.x;
                    v1.y = acc[mt][nt][3] + bvv.y;
                    *(float2*)(op + (size_t)r0 * DOUT + c) = v0;
                    *(float2*)(op + (size_t)(r0 + 8) * DOUT + c) = v1;
                }
            }
        }

        // path boundary? reload resident B (tiles per path = 256, integral)
        if (t + 1 < t1) {
            int nl = g_levels[(t + 1) / TPP];
            if (nl != curlevel) {
                curlevel = nl;
                __syncthreads();   // everyone done with old B
                load_B(sb, g_w + (size_t)curlevel * DOUT * DIN, tid);
                CP_COMMIT();
                CP_WAIT0();
                __syncthreads();
            }
        }
    }
}

// ---------------- launch: identify inputs BY ELEMENT COUNT ----------------
extern "C" void kernel_launch(void* const* d_in, const int* in_sizes, int n_in,
                              void* d_out, int out_size) {
    const float* x = nullptr;
    const float* weight_bank = nullptr;
    const float* bias = nullptr;
    const void* abits = nullptr;

    for (int i = 0; i < n_in; i++) {
        int s = in_sizes[i];
        if (s == M_TOTAL * DIN)             x = (const float*)d_in[i];
        else if (s == LEVELS * DOUT * DIN)  weight_bank = (const float*)d_in[i];
        else if (s == DOUT)                 bias = (const float*)d_in[i];
        else if (s == PN)                   abits = d_in[i];
    }

    float* out = (float*)d_out;

    cudaFuncSetAttribute(mpl_kernel, cudaFuncAttributeMaxDynamicSharedMemorySize, SMEM_BYTES);

    mpl_prep<<<(LEVELS * DOUT * DIN + 255) / 256, 256>>>(weight_bank, abits);
    mpl_kernel<<<NCTA, NTHREADS, SMEM_BYTES>>>(x, bias, out);
}